// round 2
// baseline (speedup 1.0000x reference)
#include <cuda_runtime.h>

// LZC48: out[t] = 6-bit MSB-first float encoding of the index of the first
// nonzero among X[t*48 .. t*48+47]; 48 (0b110000) if all zero. Inputs are
// exact {0.0f, 1.0f}, so bit-level integer logic reproduces the soft-gate
// reference exactly (rel_err = 0).
//
// Memory strategy: one thread per 48-float word (192 B, 32B-aligned).
// Unconditionally load only the first 32B DRAM sector (bits 0..7) — this
// decides the answer with prob 1 - 2^-8. A rare, non-hoisted fallback loop
// reads the remaining 10 float4s with early exit. Expected DRAM read traffic
// ~= 1 sector/word (64 MiB) instead of 6 (384 MiB). Output writes are
// 24 B/thread, warp-contiguous -> every written sector fully covered.

__global__ __launch_bounds__(256) void lzc48_kernel(
    const uint4* __restrict__ X, float* __restrict__ out, int n_words)
{
    int t = blockIdx.x * blockDim.x + threadIdx.x;
    if (t >= n_words) return;

    const uint4* p = X + (size_t)t * 12;    // 48 floats = 12 uint4
    uint4 v0 = __ldcs(p);                   // bytes [0,16): bits 0..3
    uint4 v1 = __ldcs(p + 1);               // bytes [16,32): bits 4..7

    // Branchless first-set-bit over bits 0..7. Reverse-order predicated
    // writes: smallest index applied last wins.
    int lzc = 48;
    if (v1.w != 0u) lzc = 7;
    if (v1.z != 0u) lzc = 6;
    if (v1.y != 0u) lzc = 5;
    if (v1.x != 0u) lzc = 4;
    if (v0.w != 0u) lzc = 3;
    if (v0.z != 0u) lzc = 2;
    if (v0.y != 0u) lzc = 1;
    if (v0.x != 0u) lzc = 0;

    if (lzc == 48) {                        // cold path: prob 2^-8 per thread
        #pragma unroll 1
        for (int j = 2; j < 12; j++) {
            uint4 v = __ldcs(p + j);
            int base = j * 4;
            int l = 48;
            if (v.w != 0u) l = base + 3;
            if (v.z != 0u) l = base + 2;
            if (v.y != 0u) l = base + 1;
            if (v.x != 0u) l = base;
            if (l != 48) { lzc = l; break; }
        }
        // lzc stays 48 (0b110000) for the all-zero word -> encoded below.
    }

    // 6-bit MSB-first encoding as floats (LOP3 + SEL, no I2F).
    float2 a, b, c;
    a.x = (lzc & 32) ? 1.0f : 0.0f;
    a.y = (lzc & 16) ? 1.0f : 0.0f;
    b.x = (lzc &  8) ? 1.0f : 0.0f;
    b.y = (lzc &  4) ? 1.0f : 0.0f;
    c.x = (lzc &  2) ? 1.0f : 0.0f;
    c.y = (lzc &  1) ? 1.0f : 0.0f;

    // t*6 floats = t*24 B: always 8B-aligned -> three STG.64 streaming.
    float2* o = (float2*)(out + (size_t)t * 6);
    __stcs(o + 0, a);
    __stcs(o + 1, b);
    __stcs(o + 2, c);
}

extern "C" void kernel_launch(void* const* d_in, const int* in_sizes, int n_in,
                              void* d_out, int out_size)
{
    const float* X = (const float*)d_in[0];
    float* out = (float*)d_out;
    int n_words = in_sizes[0] / 48;         // 1024*2048 = 2,097,152
    int threads = 256;
    int blocks = (n_words + threads - 1) / threads;
    lzc48_kernel<<<blocks, threads>>>((const uint4*)X, out, n_words);
}

// round 3
// speedup vs baseline: 1.0336x; 1.0336x over previous
#include <cuda_runtime.h>

// LZC48: out[t] = 6-bit MSB-first float encoding of the index of the first
// nonzero among X[t*48 .. t*48+47]; 48 (0b110000) if all zero. Inputs are
// exact {0.0f, 1.0f} floats, so bit-level integer logic is exact (rel_err=0).
//
// Read strategy (R2-validated): one thread per 192B word; probe only the
// first 32B sector (bits 0..7, decisive with prob 1-2^-8), rare non-hoisted
// fallback loop for the rest. Measured: reads sit at the 128B touched-line
// floor (~116B/word) — cannot go lower without moving input data.
//
// R3 change: outputs are staged in shared memory and written as fully
// coalesced 128B-aligned STG.128 (block's 6144B slab = 384 float4), instead
// of per-thread stride-24B STG.64 that produced partial-sector writes
// (suspected ECC read-modify-write => hidden DRAM read traffic).

__global__ __launch_bounds__(256) void lzc48_kernel(
    const uint4* __restrict__ X, float4* __restrict__ out4, int n_words)
{
    __shared__ float s[256 * 6];            // 6 KB

    int t = blockIdx.x * 256 + threadIdx.x;

    int lzc = 48;
    if (t < n_words) {
        const uint4* p = X + (size_t)t * 12;    // 48 floats = 12 uint4
        uint4 v0 = __ldcs(p);                   // bits 0..3  (bytes [0,16))
        uint4 v1 = __ldcs(p + 1);               // bits 4..7  (bytes [16,32))

        // Branchless first-set-bit over bits 0..7; smallest index applied
        // last wins.
        if (v1.w != 0u) lzc = 7;
        if (v1.z != 0u) lzc = 6;
        if (v1.y != 0u) lzc = 5;
        if (v1.x != 0u) lzc = 4;
        if (v0.w != 0u) lzc = 3;
        if (v0.z != 0u) lzc = 2;
        if (v0.y != 0u) lzc = 1;
        if (v0.x != 0u) lzc = 0;

        if (lzc == 48) {                    // cold path: prob 2^-8 per thread
            #pragma unroll 1
            for (int j = 2; j < 12; j++) {
                uint4 v = __ldcs(p + j);
                int base = j * 4;
                int l = 48;
                if (v.w != 0u) l = base + 3;
                if (v.z != 0u) l = base + 2;
                if (v.y != 0u) l = base + 1;
                if (v.x != 0u) l = base;
                if (l != 48) { lzc = l; break; }
            }
            // lzc stays 48 (0b110000) for an all-zero word.
        }
    }

    // 6-bit MSB-first encoding into smem (LOP3 + SEL, no I2F).
    float* sp = s + threadIdx.x * 6;
    sp[0] = (lzc & 32) ? 1.0f : 0.0f;
    sp[1] = (lzc & 16) ? 1.0f : 0.0f;
    sp[2] = (lzc &  8) ? 1.0f : 0.0f;
    sp[3] = (lzc &  4) ? 1.0f : 0.0f;
    sp[4] = (lzc &  2) ? 1.0f : 0.0f;
    sp[5] = (lzc &  1) ? 1.0f : 0.0f;
    __syncthreads();

    // Write the block's 6144B output slab (128B-aligned) as 384 float4s —
    // every DRAM sector/line fully covered by coalesced STG.128.
    long long total_floats = (long long)n_words * 6;
    long long blk_base_f   = (long long)blockIdx.x * 1536;   // floats
    long long blk_floats   = total_floats - blk_base_f;      // <=1536 in tail

    const float4* s4 = (const float4*)s;
    if (blk_floats >= 1536) {
        float4* o = out4 + blockIdx.x * 384;
        #pragma unroll
        for (int i = 0; i < 2; i++) {
            int idx = threadIdx.x + i * 256;
            if (idx < 384) __stcs(o + idx, s4[idx]);
        }
    } else if (blk_floats > 0) {
        // Tail block (not hit for the benchmark shape): scalar stores.
        float* o = (float*)out4 + blk_base_f;
        for (int i = threadIdx.x; i < (int)blk_floats; i += 256)
            o[i] = s[i];
    }
}

extern "C" void kernel_launch(void* const* d_in, const int* in_sizes, int n_in,
                              void* d_out, int out_size)
{
    const float* X = (const float*)d_in[0];
    int n_words = in_sizes[0] / 48;          // 1024*2048 = 2,097,152
    int blocks = (n_words + 255) / 256;      // 8192
    lzc48_kernel<<<blocks, 256>>>((const uint4*)X, (float4*)d_out, n_words);
}